// round 10
// baseline (speedup 1.0000x reference)
#include <cuda_runtime.h>
#include <cuda_fp16.h>

// Fixed problem shapes
constexpr int NN    = 50000;   // nodes
constexpr int F_IN  = 64;
constexpr int HEADS = 4;
constexpr int HID   = 32;
constexpr int C1    = HEADS * HID;  // 128
constexpr int C2    = HID;          // 32
constexpr int CLS   = 3;
constexpr int SLOTS = 96;           // bucket capacity per node (deg ~ Poisson(17))
constexpr int PB    = 64;           // partial accumulator buckets

// ---------------- scratch (device globals) ----------------------------------
__device__ __align__(16) __half g_h1h[NN * C1];   // fp16 layer-1 features
__device__ __align__(16) float g_asrc1[NN * HEADS];
__device__ __align__(16) float g_adst1[NN * HEADS];
__device__ __align__(16) float g_out1[NN * C1];
__device__ __align__(16) __half g_h2h[NN * C2];   // fp16 layer-2 features
__device__ float g_asrc2[NN];
__device__ float g_adst2[NN];
__device__ float g_paccum[PB * C2];               // partial global sums
__device__ int   g_ei64;

// bucket CSR
__device__ int g_cursor[NN];                      // becomes degree after scatter
__device__ int g_sortbuf[NN * SLOTS];

// ---------------- init: self-loop preplacement + dtype detect ----------------
__global__ void k_init(const int* __restrict__ ei, int n) {
    int i = blockIdx.x * blockDim.x + threadIdx.x;
    int stride = gridDim.x * blockDim.x;
    for (; i < n; i += stride) {
        g_cursor[i] = 1;                 // slot 0 = self-loop
        g_sortbuf[i * SLOTS] = i;
        if (i < PB * C2) g_paccum[i] = 0.f;
    }
    if (blockIdx.x == 0 && threadIdx.x == 0) {
        int all_zero = 1;
        for (int j = 1; j < 512; j += 2)
            if (ei[j] != 0) { all_zero = 0; break; }
        g_ei64 = all_zero;
    }
}

__device__ __forceinline__ void load_edge(const int* ei, int idx, int E,
                                          int& src, int& dst) {
    if (g_ei64) {
        const long long* e64 = (const long long*)ei;
        src = (int)e64[idx];
        dst = (int)e64[E + idx];
    } else {
        src = ei[idx];
        dst = ei[E + idx];
    }
}

// ---------------- scatter into buckets (8 edges/thread for atomic ILP) ------
__global__ void k_scatter(const int* __restrict__ ei, int E) {
    int base = (blockIdx.x * blockDim.x + threadIdx.x) * 8;
    int srcs[8], dsts[8];
    #pragma unroll
    for (int u = 0; u < 8; u++) {
        int i = base + u;
        if (i < E) load_edge(ei, i, E, srcs[u], dsts[u]);
        else       dsts[u] = -1;
    }
    int pos[8];
    #pragma unroll
    for (int u = 0; u < 8; u++)
        if (dsts[u] >= 0) pos[u] = atomicAdd(&g_cursor[dsts[u]], 1);
    #pragma unroll
    for (int u = 0; u < 8; u++)
        if (dsts[u] >= 0) g_sortbuf[dsts[u] * SLOTS + pos[u]] = srcs[u];
}

// ---------------- K1: h1 = x @ W1 ; attn coeffs (W in registers) ------------
__global__ void __launch_bounds__(128) k_gemm1(
        const float* __restrict__ x, const float* __restrict__ W1,
        const float* __restrict__ attS, const float* __restrict__ attD, int n) {
    int t = threadIdx.x;   // output column 0..127
    float w[F_IN];
    #pragma unroll
    for (int k = 0; k < F_IN; k++) w[k] = W1[k * C1 + t];

    __shared__ float4 xsh[64 * 16];
    int n0 = blockIdx.x * 64;
    const float4* x4 = (const float4*)x;
    for (int i = t; i < 64 * 16; i += 128) {
        int node = n0 + (i >> 4);
        xsh[i] = (node < n) ? x4[node * 16 + (i & 15)] : make_float4(0.f, 0.f, 0.f, 0.f);
    }
    __syncthreads();

    float aS = attS[t], aD = attD[t];
    int lane = t & 31, wi = t >> 5;
    int nmax = min(64, n - n0);
    for (int nn = 0; nn < nmax; nn++) {
        float a0 = 0.f, a1 = 0.f, a2 = 0.f, a3 = 0.f;
        #pragma unroll
        for (int k4 = 0; k4 < 16; k4++) {
            float4 xv = xsh[nn * 16 + k4];
            a0 += xv.x * w[k4 * 4 + 0];
            a1 += xv.y * w[k4 * 4 + 1];
            a2 += xv.z * w[k4 * 4 + 2];
            a3 += xv.w * w[k4 * 4 + 3];
        }
        float acc = (a0 + a1) + (a2 + a3);
        g_h1h[(n0 + nn) * C1 + t] = __float2half(acc);
        float vs = acc * aS, vd = acc * aD;
        #pragma unroll
        for (int o = 16; o > 0; o >>= 1) {
            vs += __shfl_down_sync(0xffffffffu, vs, o);
            vd += __shfl_down_sync(0xffffffffu, vd, o);
        }
        if (lane == 0) {
            g_asrc1[(n0 + nn) * HEADS + wi] = vs;
            g_adst1[(n0 + nn) * HEADS + wi] = vd;
        }
    }
}

// ---------------- K2: edge pass 1 — 2 edges/warp-iter, half2 accumulation ---
// lanes 0-15: even edges, 16-31: odd edges. lane owns 8 channels (one uint4).
__global__ void k_edge1(int n) {
    int gw = (blockIdx.x * blockDim.x + threadIdx.x) >> 5;
    if (gw >= n) return;
    int lane = threadIdx.x & 31;
    int half = lane >> 4;          // which edge of the pair
    int l16  = lane & 15;          // channel group: ch [l16*8, l16*8+8)
    int h    = l16 >> 2;           // head (4 lanes per head)
    float aD = g_adst1[gw * HEADS + h];
    int start = gw * SLOTS, deg = g_cursor[gw];

    const uint4* h1v = reinterpret_cast<const uint4*>(g_h1h);  // 16B = 8 ch
    __half2 acc0 = __float2half2_rn(0.f), acc1 = acc0, acc2 = acc0, acc3 = acc0;
    float psum = 0.f;

    for (int i = 0; i < deg; i += 32) {
        int myj = i + lane;
        int s = (myj < deg) ? g_sortbuf[start + myj] : -1;
        #pragma unroll
        for (int b = 0; b < 4; b++) {             // sub-blocks of 8 edges (4 pairs)
            if (i + b * 8 < deg) {                // warp-uniform guard
                #pragma unroll
                for (int t = 0; t < 4; t++) {
                    int j = b * 8 + t * 2 + half; // this half's edge in batch
                    int src = __shfl_sync(0xffffffffu, s, j);
                    int srcc = max(src, 0);
                    float e = g_asrc1[srcc * HEADS + h] + aD;
                    e = fmaxf(e, 0.2f * e);
                    float p = (src >= 0) ? __expf(e) : 0.f;
                    uint4 raw = h1v[srcc * 16 + l16];
                    __half2 ph = __float2half2_rn(p);
                    acc0 = __hfma2(ph, *reinterpret_cast<__half2*>(&raw.x), acc0);
                    acc1 = __hfma2(ph, *reinterpret_cast<__half2*>(&raw.y), acc1);
                    acc2 = __hfma2(ph, *reinterpret_cast<__half2*>(&raw.z), acc2);
                    acc3 = __hfma2(ph, *reinterpret_cast<__half2*>(&raw.w), acc3);
                    psum += p;
                }
            }
        }
    }

    // expand to fp32 and combine the two halves
    float a[8];
    {
        float2 f0 = __half22float2(acc0), f1 = __half22float2(acc1);
        float2 f2 = __half22float2(acc2), f3 = __half22float2(acc3);
        a[0] = f0.x; a[1] = f0.y; a[2] = f1.x; a[3] = f1.y;
        a[4] = f2.x; a[5] = f2.y; a[6] = f3.x; a[7] = f3.y;
    }
    #pragma unroll
    for (int k = 0; k < 8; k++)
        a[k] += __shfl_xor_sync(0xffffffffu, a[k], 16);
    psum += __shfl_xor_sync(0xffffffffu, psum, 16);

    if (half == 0) {
        float inv = 1.0f / psum;
        float4* outp = reinterpret_cast<float4*>(g_out1) + gw * 32 + l16 * 2;
        outp[0] = make_float4(a[0] * inv, a[1] * inv, a[2] * inv, a[3] * inv);
        outp[1] = make_float4(a[4] * inv, a[5] * inv, a[6] * inv, a[7] * inv);
    }
}

// ---------------- K3: bias+ELU, GEMM2 (W2 k-chunks in regs), attn coeffs ----
__global__ void __launch_bounds__(256) k_node1(
        const float* __restrict__ W2, const float* __restrict__ b1,
        const float* __restrict__ attS2, const float* __restrict__ attD2, int n) {
    int tx = threadIdx.x;        // col 0..31
    int ty = threadIdx.y;        // k-chunk 0..7
    int t = ty * 32 + tx;

    float w2r[16];
    #pragma unroll
    for (int k = 0; k < 16; k++) w2r[k] = W2[(ty * 16 + k) * C2 + tx];

    __shared__ float hsh[16 * C1];
    __shared__ float ps[8][16][32];

    int n0 = blockIdx.x * 16;
    for (int i = t; i < 16 * C1; i += 256) {
        int nn = i >> 7, k = i & 127;
        int node = n0 + nn;
        float v = 0.f;
        if (node < n) {
            v = g_out1[node * C1 + k] + b1[k];
            v = v > 0.f ? v : expm1f(v);
        }
        hsh[i] = v;
    }
    __syncthreads();

    const float4* h4 = (const float4*)hsh;
    for (int nn = 0; nn < 16; nn++) {
        float acc = 0.f;
        #pragma unroll
        for (int k4 = 0; k4 < 4; k4++) {
            float4 hv = h4[nn * 32 + ty * 4 + k4];
            acc += hv.x * w2r[k4 * 4 + 0] + hv.y * w2r[k4 * 4 + 1]
                 + hv.z * w2r[k4 * 4 + 2] + hv.w * w2r[k4 * 4 + 3];
        }
        ps[ty][nn][tx] = acc;
    }
    __syncthreads();

    float aS = attS2[tx], aD = attD2[tx];
    #pragma unroll
    for (int pp = 0; pp < 2; pp++) {
        int nn = pp * 8 + (t >> 5);
        int col = tx;
        float s = 0.f;
        #pragma unroll
        for (int j = 0; j < 8; j++) s += ps[j][nn][col];
        int node = n0 + nn;
        float vs = s * aS, vd = s * aD;
        #pragma unroll
        for (int o = 16; o > 0; o >>= 1) {
            vs += __shfl_down_sync(0xffffffffu, vs, o);
            vd += __shfl_down_sync(0xffffffffu, vd, o);
        }
        if (node < n) {
            g_h2h[node * C2 + col] = __float2half(s);
            if (col == 0) { g_asrc2[node] = vs; g_adst2[node] = vd; }
        }
    }
}

// ---------------- K4: edge pass 2 + fused global-sum -------------------------
__global__ void k_edge2(int n) {
    __shared__ float sblock[C2];
    int t = threadIdx.x;
    if (t < C2) sblock[t] = 0.f;
    __syncthreads();

    int gw = (blockIdx.x * blockDim.x + t) >> 5;
    int lane = t & 31;
    if (gw < n) {
        int g = lane >> 3, l8 = lane & 7;
        float aD = g_adst2[gw];
        int start = gw * SLOTS, deg = g_cursor[gw];

        const uint2* h2v = reinterpret_cast<const uint2*>(g_h2h);
        float4 acc = make_float4(0.f, 0.f, 0.f, 0.f);
        float psum = 0.f;
        #pragma unroll 4
        for (int i = g; i < deg; i += 4) {
            int src = g_sortbuf[start + i];
            float e = g_asrc2[src] + aD;
            e = fmaxf(e, 0.2f * e);
            float p = __expf(e);
            uint2 raw = h2v[src * 8 + l8];
            float2 f01 = __half22float2(*reinterpret_cast<__half2*>(&raw.x));
            float2 f23 = __half22float2(*reinterpret_cast<__half2*>(&raw.y));
            acc.x += p * f01.x; acc.y += p * f01.y;
            acc.z += p * f23.x; acc.w += p * f23.y;
            psum += p;
        }
        #pragma unroll
        for (int o = 8; o <= 16; o <<= 1) {
            acc.x += __shfl_xor_sync(0xffffffffu, acc.x, o);
            acc.y += __shfl_xor_sync(0xffffffffu, acc.y, o);
            acc.z += __shfl_xor_sync(0xffffffffu, acc.z, o);
            acc.w += __shfl_xor_sync(0xffffffffu, acc.w, o);
            psum  += __shfl_xor_sync(0xffffffffu, psum,  o);
        }
        if (lane < 8) {
            float inv = 1.0f / psum;
            int c = lane * 4;
            atomicAdd(&sblock[c + 0], acc.x * inv);
            atomicAdd(&sblock[c + 1], acc.y * inv);
            atomicAdd(&sblock[c + 2], acc.z * inv);
            atomicAdd(&sblock[c + 3], acc.w * inv);
        }
    }
    __syncthreads();
    if (t < C2)
        atomicAdd(&g_paccum[(blockIdx.x & (PB - 1)) * C2 + t], sblock[t]);
}

// ---------------- K5: reduce partials -> mean -> logits -> softmax -----------
__global__ void k_out(const float* __restrict__ b2,
                      const float* __restrict__ linW, const float* __restrict__ linb,
                      float* __restrict__ out, int n) {
    __shared__ float tot[C2];
    int t = threadIdx.x;   // 32 threads
    float s = 0.f;
    for (int b = 0; b < PB; b++) s += g_paccum[b * C2 + t];
    tot[t] = s / (float)n + b2[t];
    __syncwarp();
    if (t == 0) {
        float logits[CLS];
        for (int j = 0; j < CLS; j++) {
            float acc = linb[j];
            for (int c = 0; c < C2; c++)
                acc += tot[c] * linW[c * CLS + j];
            logits[j] = acc;
        }
        float m = fmaxf(logits[0], fmaxf(logits[1], logits[2]));
        float e0 = expf(logits[0] - m);
        float e1 = expf(logits[1] - m);
        float e2 = expf(logits[2] - m);
        float sm = e0 + e1 + e2;
        out[0] = e0 / sm; out[1] = e1 / sm; out[2] = e2 / sm;
    }
}

// ---------------- launcher ---------------------------------------------------
extern "C" void kernel_launch(void* const* d_in, const int* in_sizes, int n_in,
                              void* d_out, int out_size) {
    const float* x        = (const float*)d_in[0];
    const float* W1       = (const float*)d_in[1];
    const float* att_src1 = (const float*)d_in[2];
    const float* att_dst1 = (const float*)d_in[3];
    const float* b1       = (const float*)d_in[4];
    const float* W2       = (const float*)d_in[5];
    const float* att_src2 = (const float*)d_in[6];
    const float* att_dst2 = (const float*)d_in[7];
    const float* b2       = (const float*)d_in[8];
    const float* linW     = (const float*)d_in[9];
    const float* linb     = (const float*)d_in[10];
    const int*   ei       = (const int*)d_in[11];

    int n  = in_sizes[0] / F_IN;       // 50000
    int E  = in_sizes[11] / 2;         // 800000
    float* out = (float*)d_out;

    k_init<<<64, 256>>>(ei, n);
    k_scatter<<<(E + 2047) / 2048, 256>>>(ei, E);

    k_gemm1<<<(n + 63) / 64, 128>>>(x, W1, att_src1, att_dst1, n);

    {
        long long threads = (long long)n * 32;
        k_edge1<<<(int)((threads + 255) / 256), 256>>>(n);
    }

    k_node1<<<(n + 15) / 16, dim3(32, 8)>>>(W2, b1, att_src2, att_dst2, n);

    {
        long long threads = (long long)n * 32;
        k_edge2<<<(int)((threads + 255) / 256), 256>>>(n);
    }

    k_out<<<1, 32>>>(b2, linW, linb, out, n);
}